// round 5
// baseline (speedup 1.0000x reference)
#include <cuda_runtime.h>
#include <cstdint>

#define T_STEPS 1024
#define B_SZ    64
#define H_SZ    512
#define IN_SZ   512
#define G4      2048
#define NCTA    128
#define NGRP    4          // independent batch groups
#define CPG     32         // CTAs per group
#define BPG     16         // batches per group
#define UPC     16         // hidden units per CTA

#define WS2 68             // ws[k][64 rows] pad: ks lanes -> 1-phase LDS.128
#define HS2 24             // hs[k][16 b]    pad: ks lanes -> 2-phase LDS.64

// ---------------- scratch ----------------
__device__ float    g_xpT[(size_t)T_STEPS * G4 * B_SZ];            // [t][g][b]
__device__ float    g_hT [(size_t)T_STEPS * NGRP * H_SZ * BPG];    // [t][grp][k][b]
__device__ unsigned g_arrive[NCTA];                                // barrier flags

// ---------------- helpers ----------------
__device__ __forceinline__ float sigf(float x) { return 1.0f / (1.0f + __expf(-x)); }
__device__ __forceinline__ float tanh_fast(float x) {
    float ax = fabsf(x);
    float e  = __expf(-2.0f * ax);
    float t  = (1.0f - e) / (1.0f + e);
    return copysignf(t, x);
}
__device__ __forceinline__ unsigned smem_u32(const void* p) {
    return (unsigned)__cvta_generic_to_shared(p);
}
__device__ __forceinline__ void cp_async16(unsigned dst, const void* src) {
    asm volatile("cp.async.ca.shared.global [%0], [%1], 16;" :: "r"(dst), "l"(src));
}
__device__ __forceinline__ void cp_commit() {
    asm volatile("cp.async.commit_group;" ::: "memory");
}
__device__ __forceinline__ void cp_wait1() {
    asm volatile("cp.async.wait_group 1;" ::: "memory");
}
__device__ __forceinline__ void cp_wait0() {
    asm volatile("cp.async.wait_group 0;" ::: "memory");
}

// packed fp32x2 FMA (PTX-only on Blackwell)
__device__ __forceinline__ void fma2(unsigned long long& d,
                                     unsigned long long a, unsigned long long b) {
    asm("fma.rn.f32x2 %0, %1, %2, %0;" : "+l"(d) : "l"(a), "l"(b));
}
__device__ __forceinline__ unsigned long long pack2(float x, float y) {
    unsigned long long r;
    asm("mov.b64 %0, {%1, %2};" : "=l"(r) : "f"(x), "f"(y));
    return r;
}
__device__ __forceinline__ float2 unpack2(unsigned long long v) {
    float2 f;
    asm("mov.b64 {%0, %1}, %2;" : "=f"(f.x), "=f"(f.y) : "l"(v));
    return f;
}
__device__ __forceinline__ void lds_v2u64(unsigned long long& a, unsigned long long& b,
                                          unsigned addr) {
    asm volatile("ld.shared.v2.u64 {%0, %1}, [%2];" : "=l"(a), "=l"(b) : "r"(addr));
}
__device__ __forceinline__ void lds_v2f32(float& a, float& b, unsigned addr) {
    asm volatile("ld.shared.v2.f32 {%0, %1}, [%2];" : "=f"(a), "=f"(b) : "r"(addr));
}
__device__ __forceinline__ void sts_f32(unsigned addr, float a) {
    asm volatile("st.shared.f32 [%0], %1;" :: "r"(addr), "f"(a));
}

// Group barrier: 32 CTAs of one batch group. Release store publishes this
// CTA's prior global writes (h) to acquire readers; monotonic across launches.
__device__ __forceinline__ void group_barrier(int ct, int gbase, int tid, unsigned target) {
    __syncthreads();
    if (tid == 0) {
        asm volatile("st.release.gpu.global.u32 [%0], %1;"
                     :: "l"(&g_arrive[ct]), "r"(target) : "memory");
    }
    if (tid < CPG) {
        unsigned v;
        do {
            asm volatile("ld.acquire.gpu.global.u32 %0, [%1];"
                         : "=r"(v) : "l"(&g_arrive[gbase + tid]) : "memory");
        } while ((int)(v - target) < 0);
    }
    __syncthreads();
}

// =====================================================================
// Phase 1: xpT[t][g][b] = x @ Wx^T + (bx + bh).  Double-buffered fp32x2 GEMM.
// M = 65536, N = 2048, K = 512. Tile 128m x 64n x 16k.
// =====================================================================
__global__ __launch_bounds__(256) void xp_gemm(
    const float* __restrict__ x,
    const float* __restrict__ Wx0, const float* __restrict__ Wx1,
    const float* __restrict__ Wx2, const float* __restrict__ Wx3,
    const float* __restrict__ bx0, const float* __restrict__ bx1,
    const float* __restrict__ bx2, const float* __restrict__ bx3,
    const float* __restrict__ bh0, const float* __restrict__ bh1,
    const float* __restrict__ bh2, const float* __restrict__ bh3)
{
    const int BM = 128, BN = 64, BK = 16;
    __shared__ __align__(16) float As[2][BK][BM];
    __shared__ __align__(16) float Bs[2][BK][BN];

    const int bxi = blockIdx.x;
    const int byi = blockIdx.y;
    const int tid = threadIdx.x;

    const int gate = bxi >> 3;
    const int gin0 = (bxi & 7) * BN;
    const float* W   = (gate == 0) ? Wx0 : (gate == 1) ? Wx1 : (gate == 2) ? Wx2 : Wx3;
    const float* bxp = (gate == 0) ? bx0 : (gate == 1) ? bx1 : (gate == 2) ? bx2 : bx3;
    const float* bhp = (gate == 0) ? bh0 : (gate == 1) ? bh1 : (gate == 2) ? bh2 : bh3;

    const int row0 = byi * BM;
    const int tm   = tid & 15;
    const int tn   = tid >> 4;

    // staging indices
    const int am0 = tid >> 2,  ak0 = tid & 3;         // + second chunk am0+64
    const int bn0 = tid >> 2,  bk0 = tid & 3;

    float4 ra0, ra1, rb;
    // prologue: tile 0
    ra0 = *(const float4*)&x[(size_t)(row0 + am0) * IN_SZ + ak0 * 4];
    ra1 = *(const float4*)&x[(size_t)(row0 + am0 + 64) * IN_SZ + ak0 * 4];
    rb  = *(const float4*)&W[(size_t)(gin0 + bn0) * IN_SZ + bk0 * 4];
    {
        As[0][ak0 * 4 + 0][am0] = ra0.x; As[0][ak0 * 4 + 1][am0] = ra0.y;
        As[0][ak0 * 4 + 2][am0] = ra0.z; As[0][ak0 * 4 + 3][am0] = ra0.w;
        As[0][ak0 * 4 + 0][am0 + 64] = ra1.x; As[0][ak0 * 4 + 1][am0 + 64] = ra1.y;
        As[0][ak0 * 4 + 2][am0 + 64] = ra1.z; As[0][ak0 * 4 + 3][am0 + 64] = ra1.w;
        Bs[0][bk0 * 4 + 0][bn0] = rb.x; Bs[0][bk0 * 4 + 1][bn0] = rb.y;
        Bs[0][bk0 * 4 + 2][bn0] = rb.z; Bs[0][bk0 * 4 + 3][bn0] = rb.w;
    }
    __syncthreads();

    unsigned long long ap[4][4];
    #pragma unroll
    for (int i = 0; i < 4; i++)
        #pragma unroll
        for (int j = 0; j < 4; j++) ap[i][j] = 0ull;

    const int NT = IN_SZ / BK;   // 32 tiles
    int p = 0;
    for (int kt = 0; kt < NT; kt++) {
        if (kt + 1 < NT) {
            int kk = (kt + 1) * BK;
            ra0 = *(const float4*)&x[(size_t)(row0 + am0) * IN_SZ + kk + ak0 * 4];
            ra1 = *(const float4*)&x[(size_t)(row0 + am0 + 64) * IN_SZ + kk + ak0 * 4];
            rb  = *(const float4*)&W[(size_t)(gin0 + bn0) * IN_SZ + kk + bk0 * 4];
        }

        const unsigned as_base = smem_u32(&As[p][0][0]);
        #pragma unroll
        for (int k = 0; k < BK; k++) {
            unsigned long long a01, a23, a45, a67;
            unsigned aaddr = as_base + (unsigned)((k * BM + tm * 8) * 4);
            lds_v2u64(a01, a23, aaddr);
            lds_v2u64(a45, a67, aaddr + 16);
            float4 bv = *(const float4*)&Bs[p][k][tn * 4];
            unsigned long long b0 = pack2(bv.x, bv.x);
            unsigned long long b1 = pack2(bv.y, bv.y);
            unsigned long long b2 = pack2(bv.z, bv.z);
            unsigned long long b3 = pack2(bv.w, bv.w);
            fma2(ap[0][0], a01, b0); fma2(ap[1][0], a23, b0);
            fma2(ap[2][0], a45, b0); fma2(ap[3][0], a67, b0);
            fma2(ap[0][1], a01, b1); fma2(ap[1][1], a23, b1);
            fma2(ap[2][1], a45, b1); fma2(ap[3][1], a67, b1);
            fma2(ap[0][2], a01, b2); fma2(ap[1][2], a23, b2);
            fma2(ap[2][2], a45, b2); fma2(ap[3][2], a67, b2);
            fma2(ap[0][3], a01, b3); fma2(ap[1][3], a23, b3);
            fma2(ap[2][3], a45, b3); fma2(ap[3][3], a67, b3);
        }

        if (kt + 1 < NT) {
            int q = p ^ 1;
            As[q][ak0 * 4 + 0][am0] = ra0.x; As[q][ak0 * 4 + 1][am0] = ra0.y;
            As[q][ak0 * 4 + 2][am0] = ra0.z; As[q][ak0 * 4 + 3][am0] = ra0.w;
            As[q][ak0 * 4 + 0][am0 + 64] = ra1.x; As[q][ak0 * 4 + 1][am0 + 64] = ra1.y;
            As[q][ak0 * 4 + 2][am0 + 64] = ra1.z; As[q][ak0 * 4 + 3][am0 + 64] = ra1.w;
            Bs[q][bk0 * 4 + 0][bn0] = rb.x; Bs[q][bk0 * 4 + 1][bn0] = rb.y;
            Bs[q][bk0 * 4 + 2][bn0] = rb.z; Bs[q][bk0 * 4 + 3][bn0] = rb.w;
        }
        __syncthreads();
        p ^= 1;
    }

    float bias[4];
    int   gcol[4];
    #pragma unroll
    for (int j = 0; j < 4; j++) {
        int gl = gin0 + tn * 4 + j;
        gcol[j] = gate * 512 + gl;
        bias[j] = bxp[gl] + bhp[gl];
    }
    #pragma unroll
    for (int mp = 0; mp < 4; mp++) {
        int M0 = row0 + tm * 8 + 2 * mp;
        size_t t0 = (size_t)(M0 >> 6);
        int b0 = M0 & 63;
        #pragma unroll
        for (int j = 0; j < 4; j++) {
            float2 v = unpack2(ap[mp][j]);
            size_t base = (t0 * G4 + gcol[j]) * B_SZ;
            g_xpT[base + b0]     = v.x + bias[j];
            g_xpT[base + b0 + 1] = v.y + bias[j];
        }
    }
}

// =====================================================================
// Phase 2: persistent recurrence. 4 independent groups x 32 CTAs.
// Group g owns batches [16g, 16g+16); CTA cw in group owns units [16cw, 16cw+16)
// -> 64 gate-rows (r = q*16 + ul), Wh slice 64x512 in SMEM (k-major, pad 68).
// h slice per group = 32 KB/step, staged k-major (pad 24).
// Thread tile: 8 rows x 2 batches x k-split-4 (shuffle reduce over ks).
// =====================================================================
__global__ __launch_bounds__(256) void lstm_rec(
    const float* __restrict__ Whf, const float* __restrict__ Whi,
    const float* __restrict__ Who, const float* __restrict__ Whg,
    float* __restrict__ out)
{
    extern __shared__ float sm[];
    float* ws  = sm;                        // [512][68]  ~136 KB
    float* hs  = ws + 512 * WS2;            // [512][24]  48 KB
    float* zbT = hs + 512 * HS2;            // [16][65]   ~4 KB
    __shared__ unsigned s_base;

    const int ct  = blockIdx.x;
    const int tid = threadIdx.x;
    const int g   = ct >> 5;            // batch group
    const int cw  = ct & 31;            // CTA within group
    const int gb  = g << 5;             // group's first CTA id
    const int j0  = cw * UPC;           // first hidden unit owned
    const int B0  = g * BPG;            // first batch owned

    // Load Wh slice transposed: ws[k*68 + r], r = q*16 + ul
    for (int idx = tid; idx < 64 * 512; idx += 256) {
        int r = idx >> 9;
        int k = idx & 511;
        int q = r >> 4, ul = r & 15;
        const float* whp = (q == 0) ? Whf : (q == 1) ? Whi : (q == 2) ? Who : Whg;
        ws[k * WS2 + r] = whp[(size_t)(j0 + ul) * H_SZ + k];
    }
    if (tid == 0) s_base = g_arrive[ct];
    __syncthreads();
    const unsigned base = s_base;

    // compute mapping: warp = row group
    const int ks = tid & 3;             // k-slice: k = 4*kk + ks
    const int bg = (tid >> 2) & 7;      // batch pair: b0 = 2*bg
    const int rg = tid >> 5;            // rows 8*rg .. 8*rg+7
    const int b0 = 2 * bg;
    const int r0 = 8 * rg;

    const unsigned ws_u = smem_u32(ws);
    const unsigned hs_u = smem_u32(hs);
    const unsigned zb_u = smem_u32(zbT);
    const unsigned wa0  = ws_u + (unsigned)((ks * WS2 + r0) * 4);
    const unsigned ha0  = hs_u + (unsigned)((ks * HS2 + b0) * 4);

    // update mapping: (unit ul, batch ub)
    const int uul = tid >> 4;           // 0..15
    const int uub = tid & 15;           // 0..15
    float c_reg = 0.0f;

    for (int t = 0; t < T_STEPS; t++) {
        // xp prefetch (independent of h)
        float xq0, xq1, xq2, xq3;
        {
            size_t xb = ((size_t)t * G4 + j0 + uul) * B_SZ + B0 + uub;
            xq0 = g_xpT[xb];
            xq1 = g_xpT[xb + (size_t)512 * B_SZ];
            xq2 = g_xpT[xb + (size_t)1024 * B_SZ];
            xq3 = g_xpT[xb + (size_t)1536 * B_SZ];
        }

        unsigned long long acc[8];
        #pragma unroll
        for (int i = 0; i < 8; i++) acc[i] = 0ull;

        if (t > 0) {
            // stage group's h_{t-1}: 32 KB, 2048 x 16B, 8 per thread, 2 groups
            const float* hsrc = g_hT + (((size_t)(t - 1) * NGRP + g) * H_SZ) * BPG;
            #pragma unroll
            for (int i = 0; i < 4; i++) {              // k < 256
                int idx = tid + i * 256;
                int k = idx >> 2, b4 = idx & 3;
                cp_async16(hs_u + (unsigned)((k * HS2 + b4 * 4) * 4),
                           hsrc + (size_t)k * BPG + b4 * 4);
            }
            cp_commit();
            #pragma unroll
            for (int i = 4; i < 8; i++) {              // k >= 256
                int idx = tid + i * 256;
                int k = idx >> 2, b4 = idx & 3;
                cp_async16(hs_u + (unsigned)((k * HS2 + b4 * 4) * 4),
                           hsrc + (size_t)k * BPG + b4 * 4);
            }
            cp_commit();

            cp_wait1();
            __syncthreads();
            #pragma unroll 4
            for (int kk = 0; kk < 64; kk++) {
                unsigned long long w01, w23, w45, w67;
                unsigned wa = wa0 + (unsigned)(kk * (4 * WS2 * 4));
                unsigned ha = ha0 + (unsigned)(kk * (4 * HS2 * 4));
                lds_v2u64(w01, w23, wa);
                lds_v2u64(w45, w67, wa + 16);
                float h0, h1; lds_v2f32(h0, h1, ha);
                unsigned long long h00 = pack2(h0, h0);
                unsigned long long h11 = pack2(h1, h1);
                fma2(acc[0], w01, h00); fma2(acc[1], w23, h00);
                fma2(acc[2], w45, h00); fma2(acc[3], w67, h00);
                fma2(acc[4], w01, h11); fma2(acc[5], w23, h11);
                fma2(acc[6], w45, h11); fma2(acc[7], w67, h11);
            }
            cp_wait0();
            __syncthreads();
            #pragma unroll 4
            for (int kk = 64; kk < 128; kk++) {
                unsigned long long w01, w23, w45, w67;
                unsigned wa = wa0 + (unsigned)(kk * (4 * WS2 * 4));
                unsigned ha = ha0 + (unsigned)(kk * (4 * HS2 * 4));
                lds_v2u64(w01, w23, wa);
                lds_v2u64(w45, w67, wa + 16);
                float h0, h1; lds_v2f32(h0, h1, ha);
                unsigned long long h00 = pack2(h0, h0);
                unsigned long long h11 = pack2(h1, h1);
                fma2(acc[0], w01, h00); fma2(acc[1], w23, h00);
                fma2(acc[2], w45, h00); fma2(acc[3], w67, h00);
                fma2(acc[4], w01, h11); fma2(acc[5], w23, h11);
                fma2(acc[6], w45, h11); fma2(acc[7], w67, h11);
            }
        }

        // reduce across the 4 k-slices (lane bits 0-1)
        #pragma unroll
        for (int i = 0; i < 8; i++) {
            float2 v = unpack2(acc[i]);
            v.x += __shfl_xor_sync(0xffffffffu, v.x, 1);
            v.y += __shfl_xor_sync(0xffffffffu, v.y, 1);
            v.x += __shfl_xor_sync(0xffffffffu, v.x, 2);
            v.y += __shfl_xor_sync(0xffffffffu, v.y, 2);
            acc[i] = pack2(v.x, v.y);
        }
        if (ks == 0) {
            #pragma unroll
            for (int p = 0; p < 4; p++) {
                float2 v0 = unpack2(acc[p]);         // rows r0+2p, r0+2p+1 @ b0
                float2 v1 = unpack2(acc[4 + p]);     // same rows @ b0+1
                unsigned e0 = zb_u + (unsigned)((b0 * 65 + r0 + 2 * p) * 4);
                unsigned e1 = zb_u + (unsigned)(((b0 + 1) * 65 + r0 + 2 * p) * 4);
                sts_f32(e0,     v0.x);
                sts_f32(e0 + 4, v0.y);
                sts_f32(e1,     v1.x);
                sts_f32(e1 + 4, v1.y);
            }
        }
        __syncthreads();

        // gate update: rows f=ul, i=16+ul, o=32+ul, g=48+ul at batch uub
        {
            float zf = zbT[uub * 65 + 0  + uul] + xq0;
            float zi = zbT[uub * 65 + 16 + uul] + xq1;
            float zo = zbT[uub * 65 + 32 + uul] + xq2;
            float zg = zbT[uub * 65 + 48 + uul] + xq3;
            float f  = sigf(zf);
            float ii = sigf(zi);
            float o  = sigf(zo);
            float gg = tanh_fast(zg);
            c_reg    = fmaf(f, c_reg, ii * gg);
            float h  = o * tanh_fast(c_reg);
            int j = j0 + uul;
            int B = B0 + uub;
            out[((size_t)t * B_SZ + B) * H_SZ + j] = h;
            g_hT[(((size_t)t * NGRP + g) * H_SZ + j) * BPG + uub] = h;
            if (t == T_STEPS - 1) {
                size_t tail = (size_t)T_STEPS * B_SZ * H_SZ;
                out[tail + (size_t)B * H_SZ + j] = h;
                out[tail + (size_t)B_SZ * H_SZ + (size_t)B * H_SZ + j] = c_reg;
            }
        }

        group_barrier(ct, gb, tid, base + (unsigned)t + 1u);
    }
}

// =====================================================================
extern "C" void kernel_launch(void* const* d_in, const int* in_sizes, int n_in,
                              void* d_out, int out_size)
{
    const float* x   = (const float*)d_in[0];
    const float* Wxf = (const float*)d_in[1];  const float* bxf = (const float*)d_in[2];
    const float* Whf = (const float*)d_in[3];  const float* bhf = (const float*)d_in[4];
    const float* Wxi = (const float*)d_in[5];  const float* bxi = (const float*)d_in[6];
    const float* Whi = (const float*)d_in[7];  const float* bhi = (const float*)d_in[8];
    const float* Wxo = (const float*)d_in[9];  const float* bxo = (const float*)d_in[10];
    const float* Who = (const float*)d_in[11]; const float* bho = (const float*)d_in[12];
    const float* Wxg = (const float*)d_in[13]; const float* bxg = (const float*)d_in[14];
    const float* Whg = (const float*)d_in[15]; const float* bhg = (const float*)d_in[16];
    float* out = (float*)d_out;

    dim3 ggrid(G4 / 64, (T_STEPS * B_SZ) / 128);
    xp_gemm<<<ggrid, 256>>>(x, Wxf, Wxi, Wxo, Wxg,
                            bxf, bxi, bxo, bxg,
                            bhf, bhi, bho, bhg);

    const int smem_bytes = (512 * WS2 + 512 * HS2 + 16 * 65) * 4;
    cudaFuncSetAttribute(lstm_rec, cudaFuncAttributeMaxDynamicSharedMemorySize, smem_bytes);
    lstm_rec<<<NCTA, 256, smem_bytes>>>(Whf, Whi, Who, Whg, out);
}